// round 15
// baseline (speedup 1.0000x reference)
#include <cuda_runtime.h>
#include <cuda_fp16.h>
#include <cstdint>

#define N_NODES_MAX 50000
#define E_MAX       800000
#define F_IN  128
#define F_HID 128
#define F_OUT 64

typedef unsigned long long ull;

// ---------------- scratch (device globals; no allocation allowed) ----------
__device__ ull   g_pack [N_NODES_MAX];                 // (cnt<<40)|fx26 wsum; zeroed in scanA
__device__ float g_dinv [N_NODES_MAX];
__device__ int   g_cnt  [N_NODES_MAX];                 // plain-stored each call
__device__ int   g_ptr  [N_NODES_MAX + 1];
__device__ int   g_cur  [N_NODES_MAX];
__device__ int   g_bsum [64];
__device__ int2  g_srt  [E_MAX];                       // (src row, norm-as-int)
__device__ __align__(16) __half g_h16[(size_t)N_NODES_MAX * F_IN];  // x@W1
__device__ __align__(16) __half g_t16[(size_t)N_NODES_MAX * F_OUT]; // fused2 out
// pre-converted weights, transposed [n][k], fp16
__device__ __align__(16) __half g_w1t[128 * 128];
__device__ __align__(16) __half g_w2t[64 * 128];

// ---------------- side stream + fork/join events (created before main) -----
struct StreamInit {
    cudaStream_t s;
    cudaEvent_t e1, e2;
    StreamInit() {
        cudaStreamCreateWithFlags(&s, cudaStreamNonBlocking);
        cudaEventCreateWithFlags(&e1, cudaEventDisableTiming);
        cudaEventCreateWithFlags(&e2, cudaEventDisableTiming);
    }
};
static StreamInit g_si;

// ---------------- helpers --------------------------------------------------
__device__ __forceinline__ int detect_is64_block(const int* ei32) {
    __shared__ int s_is64;
    if (threadIdx.x < 32) {
        int v = ei32[threadIdx.x * 2 + 1] | ei32[64 + threadIdx.x * 2 + 1];
        unsigned m = __ballot_sync(0xffffffffu, v != 0);
        if (threadIdx.x == 0) s_is64 = (m == 0u);
    }
    __syncthreads();
    return s_is64;
}

// load 4 consecutive edge indices starting at pos (pos%4==0, E%4==0)
__device__ __forceinline__ void edge_idx4(const void* ei, int is64, size_t pos,
                                          int r[4]) {
    if (is64) {
        longlong2 a = *(const longlong2*)((const long long*)ei + pos);
        longlong2 b = *(const longlong2*)((const long long*)ei + pos + 2);
        r[0] = (int)a.x; r[1] = (int)a.y; r[2] = (int)b.x; r[3] = (int)b.y;
    } else {
        int4 a = *(const int4*)((const int*)ei + pos);
        r[0] = a.x; r[1] = a.y; r[2] = a.z; r[3] = a.w;
    }
}

__device__ __forceinline__ uint32_t smem_u32(const void* p) {
    uint32_t a;
    asm("{ .reg .u64 t; cvta.to.shared.u64 t, %1; cvt.u32.u64 %0, t; }"
        : "=r"(a) : "l"(p));
    return a;
}

#define MMA_F16(c, a0, a1, a2, a3, b0, b1)                                     \
    asm volatile("mma.sync.aligned.m16n8k16.row.col.f32.f16.f16.f32 "          \
                 "{%0,%1,%2,%3}, {%4,%5,%6,%7}, {%8,%9}, {%0,%1,%2,%3};"       \
                 : "+f"((c)[0]), "+f"((c)[1]), "+f"((c)[2]), "+f"((c)[3])      \
                 : "r"(a0), "r"(a1), "r"(a2), "r"(a3), "r"(b0), "r"(b1))

__device__ __forceinline__ void ldsm4(uint32_t& r0, uint32_t& r1,
                                      uint32_t& r2, uint32_t& r3,
                                      uint32_t addr) {
    asm volatile("ldmatrix.sync.aligned.m8n8.x4.shared.b16 {%0,%1,%2,%3}, [%4];"
                 : "=r"(r0), "=r"(r1), "=r"(r2), "=r"(r3) : "r"(addr));
}

// ---------------- hist: packed deg/cnt, 4 edges/thread ---------------------
__global__ void k_hist(const void* __restrict__ ei,
                       const float* __restrict__ ew, int e) {
    int is64 = detect_is64_block((const int*)ei);
    int i0 = (blockIdx.x * blockDim.x + threadIdx.x) * 4;
    if (i0 < e) {
        int c[4];
        edge_idx4(ei, is64, (size_t)e + i0, c);
        float4 w = *(const float4*)(ew + i0);
        float wv[4] = {w.x, w.y, w.z, w.w};
#pragma unroll
        for (int j = 0; j < 4; j++) {
            ull p = (1ull << 40) | (ull)(wv[j] * 67108864.0f);   // w * 2^26
            atomicAdd(&g_pack[c[j]], p);
        }
    }
}

// ---------------- wconv: W fp16 convert (side stream) ----------------------
__global__ void k_wconv(const float* __restrict__ W1,
                        const float* __restrict__ W2) {
    int j = blockIdx.x * blockDim.x + threadIdx.x;
    if (j < 128 * 128) {
        int k = j >> 7, n = j & 127;
        g_w1t[n * 128 + k] = __float2half(W1[j]);
    } else if (j < 128 * 128 + 128 * 64) {
        int r = j - 128 * 128;
        int k = r >> 6, n = r & 63;
        g_w2t[n * 128 + k] = __float2half(W2[r]);
    }
}

// ---------------- scanA: shuffle scan + dinv + pack reset ------------------
__global__ __launch_bounds__(1024) void k_scanA(int n) {
    __shared__ int swarp[32];
    int i = blockIdx.x * 1024 + threadIdx.x;
    int lane = threadIdx.x & 31, wid = threadIdx.x >> 5;
    int cnt = 0;
    if (i < n) {
        ull p = g_pack[i];
        cnt = (int)(p >> 40);
        float wsum = (float)(p & 0xFFFFFFFFFFull) * (1.0f / 67108864.0f);
        g_dinv[i] = rsqrtf(wsum + 1.0f);   // + self loop
        g_pack[i] = 0ull;                  // reset for replay
        g_cnt[i] = cnt;
    }
    int v = cnt;
#pragma unroll
    for (int o = 1; o < 32; o <<= 1) {
        int t = __shfl_up_sync(0xffffffffu, v, o);
        if (lane >= o) v += t;
    }
    if (lane == 31) swarp[wid] = v;
    __syncthreads();
    if (wid == 0) {
        int w = swarp[lane];
#pragma unroll
        for (int o = 1; o < 32; o <<= 1) {
            int t = __shfl_up_sync(0xffffffffu, w, o);
            if (lane >= o) w += t;
        }
        swarp[lane] = w;
    }
    __syncthreads();
    int incl = v + (wid ? swarp[wid - 1] : 0);
    if (i < n) g_ptr[i] = incl;                        // inclusive
    if (threadIdx.x == 1023) g_bsum[blockIdx.x] = incl;
}

// ---------------- scanBC: block-sum scan (redundant per block) + finalize ---
__global__ void k_scanBC(int n, int nb) {
    __shared__ int sb[64];
    int v0 = 0;
    if (threadIdx.x < 64) {
        v0 = (threadIdx.x < nb) ? g_bsum[threadIdx.x] : 0;
        sb[threadIdx.x] = v0;
    }
    __syncthreads();
#pragma unroll
    for (int off = 1; off < 64; off <<= 1) {
        int t = (threadIdx.x >= off && threadIdx.x < 64) ? sb[threadIdx.x - off] : 0;
        __syncthreads();
        if (threadIdx.x < 64) sb[threadIdx.x] += t;
        __syncthreads();
    }
    if (threadIdx.x < 64) sb[threadIdx.x] -= v0;   // exclusive
    __syncthreads();

    int i = blockIdx.x * blockDim.x + threadIdx.x;
    if (i < n) {
        int cnt = g_cnt[i];
        int excl = g_ptr[i] - cnt + sb[i >> 10];
        g_ptr[i] = excl;
        g_cur[i] = excl;
        if (i == n - 1) g_ptr[n] = excl + cnt;
    }
}

// ---------------- place edges into CSR, 4 edges/thread ----------------------
__global__ void k_place(const void* __restrict__ ei,
                        const float* __restrict__ ew, int e) {
    int is64 = detect_is64_block((const int*)ei);
    int i0 = (blockIdx.x * blockDim.x + threadIdx.x) * 4;
    if (i0 < e) {
        int r[4], c[4];
        edge_idx4(ei, is64, (size_t)i0, r);
        edge_idx4(ei, is64, (size_t)e + i0, c);
        float4 w = *(const float4*)(ew + i0);
        float wv[4] = {w.x, w.y, w.z, w.w};
        float dr[4], dc[4];
#pragma unroll
        for (int j = 0; j < 4; j++) dr[j] = g_dinv[r[j]];
#pragma unroll
        for (int j = 0; j < 4; j++) dc[j] = g_dinv[c[j]];
#pragma unroll
        for (int j = 0; j < 4; j++) {
            float nm = dr[j] * wv[j] * dc[j];
            int pos = atomicAdd(&g_cur[c[j]], 1);
            g_srt[pos] = make_int2(r[j], __float_as_int(nm));
        }
    }
}

// smem row strides (u32 words): 36 and 68 are both ==4 (mod 32) -> conflict-free
#define SA 36
#define SA2 68

// ======== GEMM1 (fp16 mma + ldmatrix): g_h16 = fp16(x @ W1) ================
__global__ __launch_bounds__(256) void k_gemm1(const float* __restrict__ x,
                                               int M) {
    __shared__ uint32_t As[64 * SA];
    __shared__ uint32_t Bs[128 * SA];

    const int tid  = threadIdx.x;
    const int wid  = tid >> 5;
    const int lane = tid & 31;
    const int g    = lane >> 2;
    const int t    = lane & 3;
    const int rw   = wid & 3;
    const int ch2  = wid >> 2;
    const int rowbase = blockIdx.x * 64;
    const int wrow = rw * 16;

    const int lr = lane & 7, lm = lane >> 3;
    const uint32_t a_base = smem_u32(As) +
        (uint32_t)(wrow + lr + ((lm & 1) << 3)) * 144 + ((lm >> 1) << 4);
    const uint32_t b_base = smem_u32(Bs) +
        (uint32_t)(ch2 * 64 + lr + ((lm >> 1) << 3)) * 144 + ((lm & 1) << 4);

    float c[8][4];
#pragma unroll
    for (int nt = 0; nt < 8; nt++)
#pragma unroll
        for (int j = 0; j < 4; j++) c[nt][j] = 0.f;

    for (int ch = 0; ch < 2; ch++) {
        const int kb = ch * 64;
#pragma unroll
        for (int i = 0; i < 4; i++) {
            int lin = tid + i * 256;
            int row = lin >> 4;
            int kq  = lin & 15;
            int grow = rowbase + row;
            float4 f = make_float4(0.f, 0.f, 0.f, 0.f);
            if (grow < M)
                f = *(const float4*)(x + (size_t)grow * 128 + kb + kq * 4);
            __half2 p0 = __floats2half2_rn(f.x, f.y);
            __half2 p1 = __floats2half2_rn(f.z, f.w);
            int w = row * SA + kq * 2;
            As[w]     = *reinterpret_cast<uint32_t*>(&p0);
            As[w + 1] = *reinterpret_cast<uint32_t*>(&p1);
        }
#pragma unroll
        for (int i = 0; i < 4; i++) {
            int lin = tid + i * 256;
            int n = lin >> 3;
            int q = lin & 7;
            uint4 v = *(const uint4*)(g_w1t + (size_t)n * 128 + kb + q * 8);
            *(uint4*)&Bs[n * SA + q * 4] = v;
        }
        __syncthreads();

#pragma unroll
        for (int ks = 0; ks < 4; ks++) {
            const uint32_t ko = ks * 32;
            uint32_t a0, a1, a2, a3;
            ldsm4(a0, a1, a2, a3, a_base + ko);
#pragma unroll
            for (int p = 0; p < 4; p++) {
                uint32_t b0, b1, b2, b3;
                ldsm4(b0, b1, b2, b3, b_base + p * 2304u + ko);
                MMA_F16(c[2 * p],     a0, a1, a2, a3, b0, b1);
                MMA_F16(c[2 * p + 1], a0, a1, a2, a3, b2, b3);
            }
        }
        __syncthreads();
    }

    int row0 = rowbase + wrow + g;
    int row1 = row0 + 8;
#pragma unroll
    for (int nt = 0; nt < 8; nt++) {
        int n = ch2 * 64 + nt * 8 + 2 * t;
        if (row0 < M) {
            __half2 v = __floats2half2_rn(c[nt][0], c[nt][1]);
            *(__half2*)(g_h16 + (size_t)row0 * 128 + n) = v;
        }
        if (row1 < M) {
            __half2 v = __floats2half2_rn(c[nt][2], c[nt][3]);
            *(__half2*)(g_h16 + (size_t)row1 * 128 + n) = v;
        }
    }
}

// ======== fused2: per-block agg1 into smem, then gemm2 =====================
__global__ __launch_bounds__(256) void k_fused2(const float* __restrict__ b1,
                                                int n) {
    __shared__ uint32_t As[128 * SA2];   // 34816 B
    __shared__ uint32_t Bs[64 * SA];     //  9216 B

    const int tid  = threadIdx.x;
    const int wid  = tid >> 5;
    const int lane = tid & 31;
    const int g    = lane >> 2;
    const int t    = lane & 3;
    const int rowbase = blockIdx.x * 128;

    // ---- phase A: aggregate 128 nodes (warp per node, 16 iters) ----
    float4 bv = *(const float4*)(b1 + lane * 4);
#pragma unroll 1
    for (int it = 0; it < 16; it++) {
        int lrow = it * 8 + wid;
        int c = rowbase + lrow;
        uint32_t w0 = 0u, w1 = 0u;
        if (c < n) {
            int beg = g_ptr[c], end = g_ptr[c + 1];
            float sc = g_dinv[c]; sc = sc * sc;
            uint2 hv = *(const uint2*)(g_h16 + (size_t)c * 128 + lane * 4);
            float2 s0 = __half22float2(*(__half2*)&hv.x);
            float2 s1 = __half22float2(*(__half2*)&hv.y);
            float4 acc = make_float4(s0.x * sc, s0.y * sc, s1.x * sc, s1.y * sc);
            for (int e = beg; e < end; e++) {
                int2  en = g_srt[e];
                float nm = __int_as_float(en.y);
                uint2 v = *(const uint2*)(g_h16 + (size_t)en.x * 128 + lane * 4);
                float2 f0 = __half22float2(*(__half2*)&v.x);
                float2 f1 = __half22float2(*(__half2*)&v.y);
                acc.x = fmaf(f0.x, nm, acc.x);
                acc.y = fmaf(f0.y, nm, acc.y);
                acc.z = fmaf(f1.x, nm, acc.z);
                acc.w = fmaf(f1.y, nm, acc.w);
            }
            __half2 o0 = __floats2half2_rn(fmaxf(acc.x + bv.x, 0.f),
                                           fmaxf(acc.y + bv.y, 0.f));
            __half2 o1 = __floats2half2_rn(fmaxf(acc.z + bv.z, 0.f),
                                           fmaxf(acc.w + bv.w, 0.f));
            w0 = *reinterpret_cast<uint32_t*>(&o0);
            w1 = *reinterpret_cast<uint32_t*>(&o1);
        }
        As[lrow * SA2 + lane * 2]     = w0;
        As[lrow * SA2 + lane * 2 + 1] = w1;
    }

    // ---- phase B: MMA over full K=128 (A in smem), W2 chunked ----
    const int wrow = wid * 16;
    const int lr = lane & 7, lm = lane >> 3;
    const uint32_t a_base = smem_u32(As) +
        (uint32_t)(wrow + lr + ((lm & 1) << 3)) * (SA2 * 4) + ((lm >> 1) << 4);
    const uint32_t b_base = smem_u32(Bs) +
        (uint32_t)(lr + ((lm >> 1) << 3)) * 144 + ((lm & 1) << 4);

    float c[8][4];
#pragma unroll
    for (int nt = 0; nt < 8; nt++)
#pragma unroll
        for (int j = 0; j < 4; j++) c[nt][j] = 0.f;

    for (int ch = 0; ch < 2; ch++) {
        const int kb = ch * 64;
#pragma unroll
        for (int i = 0; i < 2; i++) {
            int lin = tid + i * 256;           // 512 uint4
            int nn = lin >> 3;
            int q  = lin & 7;
            uint4 v = *(const uint4*)(g_w2t + (size_t)nn * 128 + kb + q * 8);
            *(uint4*)&Bs[nn * SA + q * 4] = v;
        }
        __syncthreads();

#pragma unroll
        for (int ks = 0; ks < 4; ks++) {
            const uint32_t ko = (uint32_t)(kb * 2) + ks * 32;   // bytes into A row
            uint32_t a0, a1, a2, a3;
            ldsm4(a0, a1, a2, a3, a_base + ko);
#pragma unroll
            for (int p = 0; p < 4; p++) {
                uint32_t b0, b1, b2, b3;
                ldsm4(b0, b1, b2, b3, b_base + p * 2304u + ks * 32);
                MMA_F16(c[2 * p],     a0, a1, a2, a3, b0, b1);
                MMA_F16(c[2 * p + 1], a0, a1, a2, a3, b2, b3);
            }
        }
        __syncthreads();
    }

    int row0 = rowbase + wrow + g;
    int row1 = row0 + 8;
#pragma unroll
    for (int nt = 0; nt < 8; nt++) {
        int nn = nt * 8 + 2 * t;
        if (row0 < n) {
            __half2 v = __floats2half2_rn(c[nt][0], c[nt][1]);
            *(__half2*)(g_t16 + (size_t)row0 * 64 + nn) = v;
        }
        if (row1 < n) {
            __half2 v = __floats2half2_rn(c[nt][2], c[nt][3]);
            *(__half2*)(g_t16 + (size_t)row1 * 64 + nn) = v;
        }
    }
}

// ---- agg2: out[c] = b2 + dinv^2*t16[c] + sum nm*t16[src] -------------------
// 512 threads / 16 nodes per block
__global__ __launch_bounds__(512) void k_agg2(const float* __restrict__ b2,
                                              float* __restrict__ out, int n) {
    int c = blockIdx.x * 16 + (threadIdx.x >> 5);
    if (c >= n) return;
    int lane = threadIdx.x & 31;
    int beg = g_ptr[c], end = g_ptr[c + 1];

    float sc = g_dinv[c]; sc = sc * sc;
    __half2 hv = *(const __half2*)(g_t16 + (size_t)c * 64 + lane * 2);
    float2 self = __half22float2(hv);
    float2 acc = make_float2(__ldg(b2 + lane * 2)     + self.x * sc,
                             __ldg(b2 + lane * 2 + 1) + self.y * sc);

    for (int e = beg; e < end; e++) {
        int2  en = g_srt[e];
        float nm = __int_as_float(en.y);
        __half2 v = *(const __half2*)(g_t16 + (size_t)en.x * 64 + lane * 2);
        float2 f = __half22float2(v);
        acc.x = fmaf(f.x, nm, acc.x);
        acc.y = fmaf(f.y, nm, acc.y);
    }
    *(float2*)(out + (size_t)c * 64 + lane * 2) = acc;
}

// ---------------- entry ----------------------------------------------------
extern "C" void kernel_launch(void* const* d_in, const int* in_sizes, int n_in,
                              void* d_out, int out_size) {
    const float* x  = (const float*)d_in[0];
    const void*  ei = d_in[1];
    const float* ew = (const float*)d_in[2];
    const float* W1 = (const float*)d_in[3];
    const float* b1 = (const float*)d_in[4];
    const float* W2 = (const float*)d_in[5];
    const float* b2 = (const float*)d_in[6];
    float* out = (float*)d_out;

    int N = in_sizes[0] / F_IN;     // 50000
    int E = in_sizes[2];            // 800000
    int nScanBlocks = (N + 1023) / 1024;          // 49
    int E4B = (E / 4 + 255) / 256;                // 4 edges per thread
    int WB = (128 * 128 + 128 * 64 + 255) / 256;

    // fork: side stream does W convert + gemm1 (independent of CSR build)
    cudaEventRecord(g_si.e1, 0);
    cudaStreamWaitEvent(g_si.s, g_si.e1, 0);
    k_wconv<<<WB, 256, 0, g_si.s>>>(W1, W2);
    k_gemm1<<<(N + 63) / 64, 256, 0, g_si.s>>>(x, N);
    cudaEventRecord(g_si.e2, g_si.s);

    // main: CSR build chain
    k_hist  <<<E4B, 256>>>(ei, ew, E);
    k_scanA <<<nScanBlocks, 1024>>>(N);
    k_scanBC<<<(N + 255) / 256, 256>>>(N, nScanBlocks);
    k_place <<<E4B, 256>>>(ei, ew, E);

    // join, then fused agg1+gemm2 and agg2
    cudaStreamWaitEvent(0, g_si.e2, 0);
    k_fused2<<<(N + 127) / 128, 256>>>(b1, N);
    k_agg2  <<<(N + 15) / 16, 512>>>(b2, out, N);
}

// round 16
// speedup vs baseline: 1.0176x; 1.0176x over previous
#include <cuda_runtime.h>
#include <cuda_fp16.h>
#include <cstdint>

#define N_NODES_MAX 50000
#define E_MAX       800000
#define F_IN  128
#define F_HID 128
#define F_OUT 64

typedef unsigned long long ull;

// ---------------- scratch (device globals; no allocation allowed) ----------
__device__ ull   g_pack  [N_NODES_MAX];            // (cnt<<40)|fx26 wsum; zeroed in scan
__device__ float g_dinv  [N_NODES_MAX];
__device__ int   g_ptr   [N_NODES_MAX + 1];
__device__ int   g_cur   [N_NODES_MAX];
__device__ ull   g_bsum64[64];                     // (1<<63)|aggregate; zeroed in place
__device__ int2  g_srt   [E_MAX];                  // (src row, norm-as-int)
__device__ __align__(16) __half g_h16[(size_t)N_NODES_MAX * F_IN];  // x@W1
__device__ __align__(16) __half g_t16[(size_t)N_NODES_MAX * F_OUT]; // fused2 out
// pre-converted weights, transposed [n][k], fp16
__device__ __align__(16) __half g_w1t[128 * 128];
__device__ __align__(16) __half g_w2t[64 * 128];

// ---------------- side stream + fork/join events (created before main) -----
struct StreamInit {
    cudaStream_t s;
    cudaEvent_t e1, e2;
    StreamInit() {
        cudaStreamCreateWithFlags(&s, cudaStreamNonBlocking);
        cudaEventCreateWithFlags(&e1, cudaEventDisableTiming);
        cudaEventCreateWithFlags(&e2, cudaEventDisableTiming);
    }
};
static StreamInit g_si;

// ---------------- helpers --------------------------------------------------
__device__ __forceinline__ int edge_idx(const void* ei, int is64, size_t pos) {
    if (is64) return (int)((const long long*)ei)[pos];
    return ((const int*)ei)[pos];
}

__device__ __forceinline__ int detect_is64_block(const int* ei32) {
    __shared__ int s_is64;
    if (threadIdx.x < 32) {
        int v = ei32[threadIdx.x * 2 + 1] | ei32[64 + threadIdx.x * 2 + 1];
        unsigned m = __ballot_sync(0xffffffffu, v != 0);
        if (threadIdx.x == 0) s_is64 = (m == 0u);
    }
    __syncthreads();
    return s_is64;
}

__device__ __forceinline__ uint32_t smem_u32(const void* p) {
    uint32_t a;
    asm("{ .reg .u64 t; cvta.to.shared.u64 t, %1; cvt.u32.u64 %0, t; }"
        : "=r"(a) : "l"(p));
    return a;
}

#define MMA_F16(c, a0, a1, a2, a3, b0, b1)                                     \
    asm volatile("mma.sync.aligned.m16n8k16.row.col.f32.f16.f16.f32 "          \
                 "{%0,%1,%2,%3}, {%4,%5,%6,%7}, {%8,%9}, {%0,%1,%2,%3};"       \
                 : "+f"((c)[0]), "+f"((c)[1]), "+f"((c)[2]), "+f"((c)[3])      \
                 : "r"(a0), "r"(a1), "r"(a2), "r"(a3), "r"(b0), "r"(b1))

__device__ __forceinline__ void ldsm4(uint32_t& r0, uint32_t& r1,
                                      uint32_t& r2, uint32_t& r3,
                                      uint32_t addr) {
    asm volatile("ldmatrix.sync.aligned.m8n8.x4.shared.b16 {%0,%1,%2,%3}, [%4];"
                 : "=r"(r0), "=r"(r1), "=r"(r2), "=r"(r3) : "r"(addr));
}

// ---------------- hist: packed deg/cnt in ONE 64-bit atomic ----------------
__global__ void k_hist(const void* __restrict__ ei,
                       const float* __restrict__ ew, int e) {
    int is64 = detect_is64_block((const int*)ei);
    int i = blockIdx.x * blockDim.x + threadIdx.x;
    if (i < e) {
        int c = edge_idx(ei, is64, (size_t)e + i);
        ull p = (1ull << 40) | (ull)(ew[i] * 67108864.0f);   // w * 2^26
        atomicAdd(&g_pack[c], p);
    }
}

// ---------------- wconv: W fp16 convert (side stream) ----------------------
__global__ void k_wconv(const float* __restrict__ W1,
                        const float* __restrict__ W2) {
    int j = blockIdx.x * blockDim.x + threadIdx.x;
    if (j < 128 * 128) {
        int k = j >> 7, n = j & 127;
        g_w1t[n * 128 + k] = __float2half(W1[j]);
    } else if (j < 128 * 128 + 128 * 64) {
        int r = j - 128 * 128;
        int k = r >> 6, n = r & 63;
        g_w2t[n * 128 + k] = __float2half(W2[r]);
    }
}

// ---------------- scan: single-pass scan + dinv + pack reset ---------------
// 49 blocks, all resident in wave 1. Each block publishes its aggregate as
// (1<<63)|total in ONE 64-bit word; every block spins (in parallel) on the
// aggregates of lower-indexed blocks. g_bsum64 is zeroed by k_place for the
// next replay; BSS zero covers the first call.
__global__ __launch_bounds__(1024) void k_scan(int n) {
    __shared__ int swarp[32];
    __shared__ int s_pref[2];
    const int tid  = threadIdx.x;
    const int lane = tid & 31, wid = tid >> 5;
    const int b    = blockIdx.x;
    int i = b * 1024 + tid;

    int cnt = 0;
    if (i < n) {
        ull p = g_pack[i];
        cnt = (int)(p >> 40);
        float wsum = (float)(p & 0xFFFFFFFFFFull) * (1.0f / 67108864.0f);
        g_dinv[i] = rsqrtf(wsum + 1.0f);   // + self loop
        g_pack[i] = 0ull;                  // reset for replay
    }
    // local inclusive scan
    int v = cnt;
#pragma unroll
    for (int o = 1; o < 32; o <<= 1) {
        int t = __shfl_up_sync(0xffffffffu, v, o);
        if (lane >= o) v += t;
    }
    if (lane == 31) swarp[wid] = v;
    __syncthreads();
    if (wid == 0) {
        int w = swarp[lane];
#pragma unroll
        for (int o = 1; o < 32; o <<= 1) {
            int t = __shfl_up_sync(0xffffffffu, w, o);
            if (lane >= o) w += t;
        }
        swarp[lane] = w;
    }
    __syncthreads();
    int incl = v + (wid ? swarp[wid - 1] : 0);
    int total = swarp[31];

    // publish aggregate (flag+value in one word)
    if (tid == 0)
        *(volatile ull*)&g_bsum64[b] = (1ull << 63) | (ull)(unsigned)total;

    // parallel lookback: threads 0..63 cover predecessor slots
    int part = 0;
    if (tid < 64) {
        if (tid < b) {
            volatile ull* slot = &g_bsum64[tid];
            ull x;
            do { x = *slot; } while (!(x >> 63));
            part = (int)(unsigned)(x & 0xFFFFFFFFull);
        }
#pragma unroll
        for (int o = 16; o; o >>= 1)
            part += __shfl_xor_sync(0xffffffffu, part, o);
        if (lane == 0) s_pref[wid] = part;
    }
    __syncthreads();
    int prefix = s_pref[0] + s_pref[1];

    if (i < n) {
        int excl = prefix + incl - cnt;
        g_ptr[i] = excl;
        g_cur[i] = excl;
        if (i == n - 1) g_ptr[n] = excl + cnt;
    }
}

// ---------------- place edges into CSR: store (src, norm) -------------------
__global__ void k_place(const void* __restrict__ ei,
                        const float* __restrict__ ew, int e) {
    // reset scan flags for the next replay (runs strictly after k_scan)
    if (blockIdx.x == 0 && threadIdx.x < 64) g_bsum64[threadIdx.x] = 0ull;
    int is64 = detect_is64_block((const int*)ei);
    int i = blockIdx.x * blockDim.x + threadIdx.x;
    if (i < e) {
        int r = edge_idx(ei, is64, (size_t)i);
        int c = edge_idx(ei, is64, (size_t)e + i);
        float nm = g_dinv[r] * ew[i] * g_dinv[c];
        int pos = atomicAdd(&g_cur[c], 1);
        g_srt[pos] = make_int2(r, __float_as_int(nm));
    }
}

// smem row strides (u32 words): 36 and 68 are both ==4 (mod 32) -> conflict-free
#define SA 36
#define SA2 68

// ======== GEMM1 (fp16 mma + ldmatrix): g_h16 = fp16(x @ W1) ================
__global__ __launch_bounds__(256) void k_gemm1(const float* __restrict__ x,
                                               int M) {
    __shared__ uint32_t As[64 * SA];
    __shared__ uint32_t Bs[128 * SA];

    const int tid  = threadIdx.x;
    const int wid  = tid >> 5;
    const int lane = tid & 31;
    const int g    = lane >> 2;
    const int t    = lane & 3;
    const int rw   = wid & 3;
    const int ch2  = wid >> 2;
    const int rowbase = blockIdx.x * 64;
    const int wrow = rw * 16;

    const int lr = lane & 7, lm = lane >> 3;
    const uint32_t a_base = smem_u32(As) +
        (uint32_t)(wrow + lr + ((lm & 1) << 3)) * 144 + ((lm >> 1) << 4);
    const uint32_t b_base = smem_u32(Bs) +
        (uint32_t)(ch2 * 64 + lr + ((lm >> 1) << 3)) * 144 + ((lm & 1) << 4);

    float c[8][4];
#pragma unroll
    for (int nt = 0; nt < 8; nt++)
#pragma unroll
        for (int j = 0; j < 4; j++) c[nt][j] = 0.f;

    for (int ch = 0; ch < 2; ch++) {
        const int kb = ch * 64;
#pragma unroll
        for (int i = 0; i < 4; i++) {
            int lin = tid + i * 256;
            int row = lin >> 4;
            int kq  = lin & 15;
            int grow = rowbase + row;
            float4 f = make_float4(0.f, 0.f, 0.f, 0.f);
            if (grow < M)
                f = *(const float4*)(x + (size_t)grow * 128 + kb + kq * 4);
            __half2 p0 = __floats2half2_rn(f.x, f.y);
            __half2 p1 = __floats2half2_rn(f.z, f.w);
            int w = row * SA + kq * 2;
            As[w]     = *reinterpret_cast<uint32_t*>(&p0);
            As[w + 1] = *reinterpret_cast<uint32_t*>(&p1);
        }
#pragma unroll
        for (int i = 0; i < 4; i++) {
            int lin = tid + i * 256;
            int n = lin >> 3;
            int q = lin & 7;
            uint4 v = *(const uint4*)(g_w1t + (size_t)n * 128 + kb + q * 8);
            *(uint4*)&Bs[n * SA + q * 4] = v;
        }
        __syncthreads();

#pragma unroll
        for (int ks = 0; ks < 4; ks++) {
            const uint32_t ko = ks * 32;
            uint32_t a0, a1, a2, a3;
            ldsm4(a0, a1, a2, a3, a_base + ko);
#pragma unroll
            for (int p = 0; p < 4; p++) {
                uint32_t b0, b1, b2, b3;
                ldsm4(b0, b1, b2, b3, b_base + p * 2304u + ko);
                MMA_F16(c[2 * p],     a0, a1, a2, a3, b0, b1);
                MMA_F16(c[2 * p + 1], a0, a1, a2, a3, b2, b3);
            }
        }
        __syncthreads();
    }

    int row0 = rowbase + wrow + g;
    int row1 = row0 + 8;
#pragma unroll
    for (int nt = 0; nt < 8; nt++) {
        int n = ch2 * 64 + nt * 8 + 2 * t;
        if (row0 < M) {
            __half2 v = __floats2half2_rn(c[nt][0], c[nt][1]);
            *(__half2*)(g_h16 + (size_t)row0 * 128 + n) = v;
        }
        if (row1 < M) {
            __half2 v = __floats2half2_rn(c[nt][2], c[nt][3]);
            *(__half2*)(g_h16 + (size_t)row1 * 128 + n) = v;
        }
    }
}

// ======== fused2: per-block agg1 into smem, then gemm2 =====================
__global__ __launch_bounds__(256) void k_fused2(const float* __restrict__ b1,
                                                int n) {
    __shared__ uint32_t As[128 * SA2];   // 34816 B
    __shared__ uint32_t Bs[64 * SA];     //  9216 B

    const int tid  = threadIdx.x;
    const int wid  = tid >> 5;
    const int lane = tid & 31;
    const int g    = lane >> 2;
    const int t    = lane & 3;
    const int rowbase = blockIdx.x * 128;

    // ---- phase A: aggregate 128 nodes (warp per node, 16 iters) ----
    float4 bv = *(const float4*)(b1 + lane * 4);
#pragma unroll 1
    for (int it = 0; it < 16; it++) {
        int lrow = it * 8 + wid;
        int c = rowbase + lrow;
        uint32_t w0 = 0u, w1 = 0u;
        if (c < n) {
            int beg = g_ptr[c], end = g_ptr[c + 1];
            float sc = g_dinv[c]; sc = sc * sc;
            uint2 hv = *(const uint2*)(g_h16 + (size_t)c * 128 + lane * 4);
            float2 s0 = __half22float2(*(__half2*)&hv.x);
            float2 s1 = __half22float2(*(__half2*)&hv.y);
            float4 acc = make_float4(s0.x * sc, s0.y * sc, s1.x * sc, s1.y * sc);
            for (int e = beg; e < end; e++) {
                int2  en = g_srt[e];
                float nm = __int_as_float(en.y);
                uint2 v = *(const uint2*)(g_h16 + (size_t)en.x * 128 + lane * 4);
                float2 f0 = __half22float2(*(__half2*)&v.x);
                float2 f1 = __half22float2(*(__half2*)&v.y);
                acc.x = fmaf(f0.x, nm, acc.x);
                acc.y = fmaf(f0.y, nm, acc.y);
                acc.z = fmaf(f1.x, nm, acc.z);
                acc.w = fmaf(f1.y, nm, acc.w);
            }
            __half2 o0 = __floats2half2_rn(fmaxf(acc.x + bv.x, 0.f),
                                           fmaxf(acc.y + bv.y, 0.f));
            __half2 o1 = __floats2half2_rn(fmaxf(acc.z + bv.z, 0.f),
                                           fmaxf(acc.w + bv.w, 0.f));
            w0 = *reinterpret_cast<uint32_t*>(&o0);
            w1 = *reinterpret_cast<uint32_t*>(&o1);
        }
        As[lrow * SA2 + lane * 2]     = w0;
        As[lrow * SA2 + lane * 2 + 1] = w1;
    }

    // ---- phase B: MMA over full K=128 (A in smem), W2 chunked ----
    const int wrow = wid * 16;
    const int lr = lane & 7, lm = lane >> 3;
    const uint32_t a_base = smem_u32(As) +
        (uint32_t)(wrow + lr + ((lm & 1) << 3)) * (SA2 * 4) + ((lm >> 1) << 4);
    const uint32_t b_base = smem_u32(Bs) +
        (uint32_t)(lr + ((lm >> 1) << 3)) * 144 + ((lm & 1) << 4);

    float c[8][4];
#pragma unroll
    for (int nt = 0; nt < 8; nt++)
#pragma unroll
        for (int j = 0; j < 4; j++) c[nt][j] = 0.f;

    for (int ch = 0; ch < 2; ch++) {
        const int kb = ch * 64;
#pragma unroll
        for (int i = 0; i < 2; i++) {
            int lin = tid + i * 256;           // 512 uint4
            int nn = lin >> 3;
            int q  = lin & 7;
            uint4 v = *(const uint4*)(g_w2t + (size_t)nn * 128 + kb + q * 8);
            *(uint4*)&Bs[nn * SA + q * 4] = v;
        }
        __syncthreads();

#pragma unroll
        for (int ks = 0; ks < 4; ks++) {
            const uint32_t ko = (uint32_t)(kb * 2) + ks * 32;   // bytes into A row
            uint32_t a0, a1, a2, a3;
            ldsm4(a0, a1, a2, a3, a_base + ko);
#pragma unroll
            for (int p = 0; p < 4; p++) {
                uint32_t b0, b1, b2, b3;
                ldsm4(b0, b1, b2, b3, b_base + p * 2304u + ks * 32);
                MMA_F16(c[2 * p],     a0, a1, a2, a3, b0, b1);
                MMA_F16(c[2 * p + 1], a0, a1, a2, a3, b2, b3);
            }
        }
        __syncthreads();
    }

    int row0 = rowbase + wrow + g;
    int row1 = row0 + 8;
#pragma unroll
    for (int nt = 0; nt < 8; nt++) {
        int nn = nt * 8 + 2 * t;
        if (row0 < n) {
            __half2 v = __floats2half2_rn(c[nt][0], c[nt][1]);
            *(__half2*)(g_t16 + (size_t)row0 * 64 + nn) = v;
        }
        if (row1 < n) {
            __half2 v = __floats2half2_rn(c[nt][2], c[nt][3]);
            *(__half2*)(g_t16 + (size_t)row1 * 64 + nn) = v;
        }
    }
}

// ---- agg2: out[c] = b2 + dinv^2*t16[c] + sum nm*t16[src] -------------------
// 512 threads / 16 nodes per block
__global__ __launch_bounds__(512) void k_agg2(const float* __restrict__ b2,
                                              float* __restrict__ out, int n) {
    int c = blockIdx.x * 16 + (threadIdx.x >> 5);
    if (c >= n) return;
    int lane = threadIdx.x & 31;
    int beg = g_ptr[c], end = g_ptr[c + 1];

    float sc = g_dinv[c]; sc = sc * sc;
    __half2 hv = *(const __half2*)(g_t16 + (size_t)c * 64 + lane * 2);
    float2 self = __half22float2(hv);
    float2 acc = make_float2(__ldg(b2 + lane * 2)     + self.x * sc,
                             __ldg(b2 + lane * 2 + 1) + self.y * sc);

    for (int e = beg; e < end; e++) {
        int2  en = g_srt[e];
        float nm = __int_as_float(en.y);
        __half2 v = *(const __half2*)(g_t16 + (size_t)en.x * 64 + lane * 2);
        float2 f = __half22float2(v);
        acc.x = fmaf(f.x, nm, acc.x);
        acc.y = fmaf(f.y, nm, acc.y);
    }
    *(float2*)(out + (size_t)c * 64 + lane * 2) = acc;
}

// ---------------- entry ----------------------------------------------------
extern "C" void kernel_launch(void* const* d_in, const int* in_sizes, int n_in,
                              void* d_out, int out_size) {
    const float* x  = (const float*)d_in[0];
    const void*  ei = d_in[1];
    const float* ew = (const float*)d_in[2];
    const float* W1 = (const float*)d_in[3];
    const float* b1 = (const float*)d_in[4];
    const float* W2 = (const float*)d_in[5];
    const float* b2 = (const float*)d_in[6];
    float* out = (float*)d_out;

    int N = in_sizes[0] / F_IN;     // 50000
    int E = in_sizes[2];            // 800000
    int nScanBlocks = (N + 1023) / 1024;          // 49 (<= 64 slots, <=148 SMs)
    int EB = (E + 255) / 256;
    int WB = (128 * 128 + 128 * 64 + 255) / 256;

    // fork: side stream does W convert + gemm1 (independent of CSR build)
    cudaEventRecord(g_si.e1, 0);
    cudaStreamWaitEvent(g_si.s, g_si.e1, 0);
    k_wconv<<<WB, 256, 0, g_si.s>>>(W1, W2);
    k_gemm1<<<(N + 63) / 64, 256, 0, g_si.s>>>(x, N);
    cudaEventRecord(g_si.e2, g_si.s);

    // main: CSR build chain (hist -> single-pass scan -> place)
    k_hist <<<EB, 256>>>(ei, ew, E);
    k_scan <<<nScanBlocks, 1024>>>(N);
    k_place<<<EB, 256>>>(ei, ew, E);

    // join, then fused agg1+gemm2 and agg2
    cudaStreamWaitEvent(0, g_si.e2, 0);
    k_fused2<<<(N + 127) / 128, 256>>>(b1, N);
    k_agg2  <<<(N + 15) / 16, 512>>>(b2, out, N);
}

// round 17
// speedup vs baseline: 1.0395x; 1.0216x over previous
#include <cuda_runtime.h>
#include <cuda_fp16.h>
#include <cstdint>

#define N_NODES_MAX 50000
#define E_MAX       800000
#define F_IN  128
#define F_HID 128
#define F_OUT 64

typedef unsigned long long ull;

// ---------------- scratch (device globals; no allocation allowed) ----------
__device__ ull   g_pack [N_NODES_MAX];                 // (cnt<<40)|fx26 wsum; zeroed in scanA
__device__ float g_dinv [N_NODES_MAX];
__device__ int   g_cnt  [N_NODES_MAX];                 // plain-stored each call
__device__ int   g_ptr  [N_NODES_MAX + 1];
__device__ int   g_cur  [N_NODES_MAX];
__device__ int   g_bsum [64];
__device__ int2  g_srt  [E_MAX];                       // (src row, norm-as-int)
__device__ __align__(16) __half g_h16[(size_t)N_NODES_MAX * F_IN];  // x@W1
__device__ __align__(16) __half g_t16[(size_t)N_NODES_MAX * F_OUT]; // fused2 out
// pre-converted weights, transposed [n][k], fp16
__device__ __align__(16) __half g_w1t[128 * 128];
__device__ __align__(16) __half g_w2t[64 * 128];

// ---------------- side stream + fork/join events (created before main) -----
struct StreamInit {
    cudaStream_t s;
    cudaEvent_t e1, e2, e3;
    StreamInit() {
        cudaStreamCreateWithFlags(&s, cudaStreamNonBlocking);
        cudaEventCreateWithFlags(&e1, cudaEventDisableTiming);
        cudaEventCreateWithFlags(&e2, cudaEventDisableTiming);
        cudaEventCreateWithFlags(&e3, cudaEventDisableTiming);
    }
};
static StreamInit g_si;

// ---------------- helpers --------------------------------------------------
__device__ __forceinline__ int edge_idx(const void* ei, int is64, size_t pos) {
    if (is64) return (int)((const long long*)ei)[pos];
    return ((const int*)ei)[pos];
}

__device__ __forceinline__ int detect_is64_block(const int* ei32) {
    __shared__ int s_is64;
    if (threadIdx.x < 32) {
        int v = ei32[threadIdx.x * 2 + 1] | ei32[64 + threadIdx.x * 2 + 1];
        unsigned m = __ballot_sync(0xffffffffu, v != 0);
        if (threadIdx.x == 0) s_is64 = (m == 0u);
    }
    __syncthreads();
    return s_is64;
}

__device__ __forceinline__ uint32_t smem_u32(const void* p) {
    uint32_t a;
    asm("{ .reg .u64 t; cvta.to.shared.u64 t, %1; cvt.u32.u64 %0, t; }"
        : "=r"(a) : "l"(p));
    return a;
}

#define MMA_F16(c, a0, a1, a2, a3, b0, b1)                                     \
    asm volatile("mma.sync.aligned.m16n8k16.row.col.f32.f16.f16.f32 "          \
                 "{%0,%1,%2,%3}, {%4,%5,%6,%7}, {%8,%9}, {%0,%1,%2,%3};"       \
                 : "+f"((c)[0]), "+f"((c)[1]), "+f"((c)[2]), "+f"((c)[3])      \
                 : "r"(a0), "r"(a1), "r"(a2), "r"(a3), "r"(b0), "r"(b1))

__device__ __forceinline__ void ldsm4(uint32_t& r0, uint32_t& r1,
                                      uint32_t& r2, uint32_t& r3,
                                      uint32_t addr) {
    asm volatile("ldmatrix.sync.aligned.m8n8.x4.shared.b16 {%0,%1,%2,%3}, [%4];"
                 : "=r"(r0), "=r"(r1), "=r"(r2), "=r"(r3) : "r"(addr));
}

// ---------------- hist: packed deg/cnt in ONE 64-bit atomic ----------------
__global__ void k_hist(const void* __restrict__ ei,
                       const float* __restrict__ ew, int e) {
    int is64 = detect_is64_block((const int*)ei);
    int i = blockIdx.x * blockDim.x + threadIdx.x;
    if (i < e) {
        int c = edge_idx(ei, is64, (size_t)e + i);
        ull p = (1ull << 40) | (ull)(ew[i] * 67108864.0f);   // w * 2^26
        atomicAdd(&g_pack[c], p);
    }
}

// ---------------- wconv: W fp16 convert (side stream) ----------------------
__global__ void k_wconv(const float* __restrict__ W1,
                        const float* __restrict__ W2) {
    int j = blockIdx.x * blockDim.x + threadIdx.x;
    if (j < 128 * 128) {
        int k = j >> 7, n = j & 127;
        g_w1t[n * 128 + k] = __float2half(W1[j]);
    } else if (j < 128 * 128 + 128 * 64) {
        int r = j - 128 * 128;
        int k = r >> 6, n = r & 63;
        g_w2t[n * 128 + k] = __float2half(W2[r]);
    }
}

// ---------------- scanA: shuffle scan + dinv + pack reset ------------------
__global__ __launch_bounds__(1024) void k_scanA(int n) {
    __shared__ int swarp[32];
    int i = blockIdx.x * 1024 + threadIdx.x;
    int lane = threadIdx.x & 31, wid = threadIdx.x >> 5;
    int cnt = 0;
    if (i < n) {
        ull p = g_pack[i];
        cnt = (int)(p >> 40);
        float wsum = (float)(p & 0xFFFFFFFFFFull) * (1.0f / 67108864.0f);
        g_dinv[i] = rsqrtf(wsum + 1.0f);   // + self loop
        g_pack[i] = 0ull;                  // reset for replay
        g_cnt[i] = cnt;
    }
    int v = cnt;
#pragma unroll
    for (int o = 1; o < 32; o <<= 1) {
        int t = __shfl_up_sync(0xffffffffu, v, o);
        if (lane >= o) v += t;
    }
    if (lane == 31) swarp[wid] = v;
    __syncthreads();
    if (wid == 0) {
        int w = swarp[lane];
#pragma unroll
        for (int o = 1; o < 32; o <<= 1) {
            int t = __shfl_up_sync(0xffffffffu, w, o);
            if (lane >= o) w += t;
        }
        swarp[lane] = w;
    }
    __syncthreads();
    int incl = v + (wid ? swarp[wid - 1] : 0);
    if (i < n) g_ptr[i] = incl;                        // inclusive
    if (threadIdx.x == 1023) g_bsum[blockIdx.x] = incl;
}

// ---------------- scanBC: block-sum scan (redundant per block) + finalize ---
__global__ void k_scanBC(int n, int nb) {
    __shared__ int sb[64];
    int v0 = 0;
    if (threadIdx.x < 64) {
        v0 = (threadIdx.x < nb) ? g_bsum[threadIdx.x] : 0;
        sb[threadIdx.x] = v0;
    }
    __syncthreads();
#pragma unroll
    for (int off = 1; off < 64; off <<= 1) {
        int t = (threadIdx.x >= off && threadIdx.x < 64) ? sb[threadIdx.x - off] : 0;
        __syncthreads();
        if (threadIdx.x < 64) sb[threadIdx.x] += t;
        __syncthreads();
    }
    if (threadIdx.x < 64) sb[threadIdx.x] -= v0;   // exclusive
    __syncthreads();

    int i = blockIdx.x * blockDim.x + threadIdx.x;
    if (i < n) {
        int cnt = g_cnt[i];
        int excl = g_ptr[i] - cnt + sb[i >> 10];
        g_ptr[i] = excl;
        g_cur[i] = excl;
        if (i == n - 1) g_ptr[n] = excl + cnt;
    }
}

// ---------------- place edges [off, off+cnt) into CSR -----------------------
__global__ void k_place(const void* __restrict__ ei,
                        const float* __restrict__ ew, int e,
                        int off, int cnt) {
    int is64 = detect_is64_block((const int*)ei);
    int i = off + blockIdx.x * blockDim.x + threadIdx.x;
    if (i < off + cnt) {
        int r = edge_idx(ei, is64, (size_t)i);
        int c = edge_idx(ei, is64, (size_t)e + i);
        float nm = g_dinv[r] * ew[i] * g_dinv[c];
        int pos = atomicAdd(&g_cur[c], 1);
        g_srt[pos] = make_int2(r, __float_as_int(nm));
    }
}

// smem row strides (u32 words): 36 and 68 are both ==4 (mod 32) -> conflict-free
#define SA 36
#define SA2 68

// ======== GEMM1 (fp16 mma + ldmatrix): g_h16 = fp16(x @ W1) ================
__global__ __launch_bounds__(256) void k_gemm1(const float* __restrict__ x,
                                               int M) {
    __shared__ uint32_t As[64 * SA];
    __shared__ uint32_t Bs[128 * SA];

    const int tid  = threadIdx.x;
    const int wid  = tid >> 5;
    const int lane = tid & 31;
    const int g    = lane >> 2;
    const int t    = lane & 3;
    const int rw   = wid & 3;
    const int ch2  = wid >> 2;
    const int rowbase = blockIdx.x * 64;
    const int wrow = rw * 16;

    const int lr = lane & 7, lm = lane >> 3;
    const uint32_t a_base = smem_u32(As) +
        (uint32_t)(wrow + lr + ((lm & 1) << 3)) * 144 + ((lm >> 1) << 4);
    const uint32_t b_base = smem_u32(Bs) +
        (uint32_t)(ch2 * 64 + lr + ((lm >> 1) << 3)) * 144 + ((lm & 1) << 4);

    float c[8][4];
#pragma unroll
    for (int nt = 0; nt < 8; nt++)
#pragma unroll
        for (int j = 0; j < 4; j++) c[nt][j] = 0.f;

    for (int ch = 0; ch < 2; ch++) {
        const int kb = ch * 64;
#pragma unroll
        for (int i = 0; i < 4; i++) {
            int lin = tid + i * 256;
            int row = lin >> 4;
            int kq  = lin & 15;
            int grow = rowbase + row;
            float4 f = make_float4(0.f, 0.f, 0.f, 0.f);
            if (grow < M)
                f = *(const float4*)(x + (size_t)grow * 128 + kb + kq * 4);
            __half2 p0 = __floats2half2_rn(f.x, f.y);
            __half2 p1 = __floats2half2_rn(f.z, f.w);
            int w = row * SA + kq * 2;
            As[w]     = *reinterpret_cast<uint32_t*>(&p0);
            As[w + 1] = *reinterpret_cast<uint32_t*>(&p1);
        }
#pragma unroll
        for (int i = 0; i < 4; i++) {
            int lin = tid + i * 256;
            int n = lin >> 3;
            int q = lin & 7;
            uint4 v = *(const uint4*)(g_w1t + (size_t)n * 128 + kb + q * 8);
            *(uint4*)&Bs[n * SA + q * 4] = v;
        }
        __syncthreads();

#pragma unroll
        for (int ks = 0; ks < 4; ks++) {
            const uint32_t ko = ks * 32;
            uint32_t a0, a1, a2, a3;
            ldsm4(a0, a1, a2, a3, a_base + ko);
#pragma unroll
            for (int p = 0; p < 4; p++) {
                uint32_t b0, b1, b2, b3;
                ldsm4(b0, b1, b2, b3, b_base + p * 2304u + ko);
                MMA_F16(c[2 * p],     a0, a1, a2, a3, b0, b1);
                MMA_F16(c[2 * p + 1], a0, a1, a2, a3, b2, b3);
            }
        }
        __syncthreads();
    }

    int row0 = rowbase + wrow + g;
    int row1 = row0 + 8;
#pragma unroll
    for (int nt = 0; nt < 8; nt++) {
        int n = ch2 * 64 + nt * 8 + 2 * t;
        if (row0 < M) {
            __half2 v = __floats2half2_rn(c[nt][0], c[nt][1]);
            *(__half2*)(g_h16 + (size_t)row0 * 128 + n) = v;
        }
        if (row1 < M) {
            __half2 v = __floats2half2_rn(c[nt][2], c[nt][3]);
            *(__half2*)(g_h16 + (size_t)row1 * 128 + n) = v;
        }
    }
}

// ======== fused2: per-block agg1 into smem, then gemm2 =====================
__global__ __launch_bounds__(256) void k_fused2(const float* __restrict__ b1,
                                                int n) {
    __shared__ uint32_t As[128 * SA2];   // 34816 B
    __shared__ uint32_t Bs[64 * SA];     //  9216 B

    const int tid  = threadIdx.x;
    const int wid  = tid >> 5;
    const int lane = tid & 31;
    const int g    = lane >> 2;
    const int t    = lane & 3;
    const int rowbase = blockIdx.x * 128;

    // ---- phase A: aggregate 128 nodes (warp per node, 16 iters) ----
    float4 bv = *(const float4*)(b1 + lane * 4);
#pragma unroll 1
    for (int it = 0; it < 16; it++) {
        int lrow = it * 8 + wid;
        int c = rowbase + lrow;
        uint32_t w0 = 0u, w1 = 0u;
        if (c < n) {
            int beg = g_ptr[c], end = g_ptr[c + 1];
            float sc = g_dinv[c]; sc = sc * sc;
            uint2 hv = *(const uint2*)(g_h16 + (size_t)c * 128 + lane * 4);
            float2 s0 = __half22float2(*(__half2*)&hv.x);
            float2 s1 = __half22float2(*(__half2*)&hv.y);
            float4 acc = make_float4(s0.x * sc, s0.y * sc, s1.x * sc, s1.y * sc);
            for (int e = beg; e < end; e++) {
                int2  en = g_srt[e];
                float nm = __int_as_float(en.y);
                uint2 v = *(const uint2*)(g_h16 + (size_t)en.x * 128 + lane * 4);
                float2 f0 = __half22float2(*(__half2*)&v.x);
                float2 f1 = __half22float2(*(__half2*)&v.y);
                acc.x = fmaf(f0.x, nm, acc.x);
                acc.y = fmaf(f0.y, nm, acc.y);
                acc.z = fmaf(f1.x, nm, acc.z);
                acc.w = fmaf(f1.y, nm, acc.w);
            }
            __half2 o0 = __floats2half2_rn(fmaxf(acc.x + bv.x, 0.f),
                                           fmaxf(acc.y + bv.y, 0.f));
            __half2 o1 = __floats2half2_rn(fmaxf(acc.z + bv.z, 0.f),
                                           fmaxf(acc.w + bv.w, 0.f));
            w0 = *reinterpret_cast<uint32_t*>(&o0);
            w1 = *reinterpret_cast<uint32_t*>(&o1);
        }
        As[lrow * SA2 + lane * 2]     = w0;
        As[lrow * SA2 + lane * 2 + 1] = w1;
    }

    // ---- phase B: MMA over full K=128 (A in smem), W2 chunked ----
    const int wrow = wid * 16;
    const int lr = lane & 7, lm = lane >> 3;
    const uint32_t a_base = smem_u32(As) +
        (uint32_t)(wrow + lr + ((lm & 1) << 3)) * (SA2 * 4) + ((lm >> 1) << 4);
    const uint32_t b_base = smem_u32(Bs) +
        (uint32_t)(lr + ((lm >> 1) << 3)) * 144 + ((lm & 1) << 4);

    float c[8][4];
#pragma unroll
    for (int nt = 0; nt < 8; nt++)
#pragma unroll
        for (int j = 0; j < 4; j++) c[nt][j] = 0.f;

    for (int ch = 0; ch < 2; ch++) {
        const int kb = ch * 64;
#pragma unroll
        for (int i = 0; i < 2; i++) {
            int lin = tid + i * 256;           // 512 uint4
            int nn = lin >> 3;
            int q  = lin & 7;
            uint4 v = *(const uint4*)(g_w2t + (size_t)nn * 128 + kb + q * 8);
            *(uint4*)&Bs[nn * SA + q * 4] = v;
        }
        __syncthreads();

#pragma unroll
        for (int ks = 0; ks < 4; ks++) {
            const uint32_t ko = (uint32_t)(kb * 2) + ks * 32;   // bytes into A row
            uint32_t a0, a1, a2, a3;
            ldsm4(a0, a1, a2, a3, a_base + ko);
#pragma unroll
            for (int p = 0; p < 4; p++) {
                uint32_t b0, b1, b2, b3;
                ldsm4(b0, b1, b2, b3, b_base + p * 2304u + ks * 32);
                MMA_F16(c[2 * p],     a0, a1, a2, a3, b0, b1);
                MMA_F16(c[2 * p + 1], a0, a1, a2, a3, b2, b3);
            }
        }
        __syncthreads();
    }

    int row0 = rowbase + wrow + g;
    int row1 = row0 + 8;
#pragma unroll
    for (int nt = 0; nt < 8; nt++) {
        int nn = nt * 8 + 2 * t;
        if (row0 < n) {
            __half2 v = __floats2half2_rn(c[nt][0], c[nt][1]);
            *(__half2*)(g_t16 + (size_t)row0 * 64 + nn) = v;
        }
        if (row1 < n) {
            __half2 v = __floats2half2_rn(c[nt][2], c[nt][3]);
            *(__half2*)(g_t16 + (size_t)row1 * 64 + nn) = v;
        }
    }
}

// ---- agg2: out[c] = b2 + dinv^2*t16[c] + sum nm*t16[src] -------------------
// 512 threads / 16 nodes per block
__global__ __launch_bounds__(512) void k_agg2(const float* __restrict__ b2,
                                              float* __restrict__ out, int n) {
    int c = blockIdx.x * 16 + (threadIdx.x >> 5);
    if (c >= n) return;
    int lane = threadIdx.x & 31;
    int beg = g_ptr[c], end = g_ptr[c + 1];

    float sc = g_dinv[c]; sc = sc * sc;
    __half2 hv = *(const __half2*)(g_t16 + (size_t)c * 64 + lane * 2);
    float2 self = __half22float2(hv);
    float2 acc = make_float2(__ldg(b2 + lane * 2)     + self.x * sc,
                             __ldg(b2 + lane * 2 + 1) + self.y * sc);

    for (int e = beg; e < end; e++) {
        int2  en = g_srt[e];
        float nm = __int_as_float(en.y);
        __half2 v = *(const __half2*)(g_t16 + (size_t)en.x * 64 + lane * 2);
        float2 f = __half22float2(v);
        acc.x = fmaf(f.x, nm, acc.x);
        acc.y = fmaf(f.y, nm, acc.y);
    }
    *(float2*)(out + (size_t)c * 64 + lane * 2) = acc;
}

// ---------------- entry ----------------------------------------------------
extern "C" void kernel_launch(void* const* d_in, const int* in_sizes, int n_in,
                              void* d_out, int out_size) {
    const float* x  = (const float*)d_in[0];
    const void*  ei = d_in[1];
    const float* ew = (const float*)d_in[2];
    const float* W1 = (const float*)d_in[3];
    const float* b1 = (const float*)d_in[4];
    const float* W2 = (const float*)d_in[5];
    const float* b2 = (const float*)d_in[6];
    float* out = (float*)d_out;

    int N = in_sizes[0] / F_IN;     // 50000
    int E = in_sizes[2];            // 800000
    int nScanBlocks = (N + 1023) / 1024;          // 49
    int WB = (128 * 128 + 128 * 64 + 255) / 256;
    int Eh0 = E / 2;                              // first half of edges
    int Eh1 = E - Eh0;                            // second half

    // fork: side stream does W convert + gemm1 (independent of CSR build)
    cudaEventRecord(g_si.e1, 0);
    cudaStreamWaitEvent(g_si.s, g_si.e1, 0);
    k_wconv<<<WB, 256, 0, g_si.s>>>(W1, W2);
    k_gemm1<<<(N + 63) / 64, 256, 0, g_si.s>>>(x, N);

    // main: CSR build chain up to scanBC
    k_hist  <<<(E + 255) / 256, 256>>>(ei, ew, E);
    k_scanA <<<nScanBlocks, 1024>>>(N);
    k_scanBC<<<(N + 255) / 256, 256>>>(N, nScanBlocks);
    cudaEventRecord(g_si.e3, 0);                  // scanBC done

    // place split across both streams
    k_place<<<(Eh0 + 255) / 256, 256>>>(ei, ew, E, 0, Eh0);          // main
    cudaStreamWaitEvent(g_si.s, g_si.e3, 0);
    k_place<<<(Eh1 + 255) / 256, 256, 0, g_si.s>>>(ei, ew, E, Eh0, Eh1); // side
    cudaEventRecord(g_si.e2, g_si.s);

    // join, then fused agg1+gemm2 and agg2
    cudaStreamWaitEvent(0, g_si.e2, 0);
    k_fused2<<<(N + 127) / 128, 256>>>(b1, N);
    k_agg2  <<<(N + 15) / 16, 512>>>(b2, out, N);
}